// round 1
// baseline (speedup 1.0000x reference)
#include <cuda_runtime.h>
#include <math.h>

// Problem constants
#define QL 2048
#define BSZ 2
#define DM 1024
#define NH 16
#define DH 64
#define DI 4096
#define MR (QL*BSZ)      // 4096 rows of [row = i*2+b]
#define BN_ALL (BSZ*NH)  // 32 (b,n) pairs, bn = b*16+n

// ---------------- scratch (__device__ globals; no allocation allowed) ----------------
__device__ float g_wheads[(size_t)MR*3*DM];           // 4096 x 3072
__device__ float g_rk[(size_t)QL*DM];                 // 2048 x 1024
__device__ float g_qw[(size_t)BN_ALL*QL*DH];          // q + r_w_bias, per (b,n)
__device__ float g_qr[(size_t)BN_ALL*QL*DH];          // q + r_r_bias
__device__ float g_kc[(size_t)BN_ALL*QL*DH];
__device__ float g_vc[(size_t)BN_ALL*QL*DH];
__device__ float g_rkc[(size_t)NH*QL*DH];             // r_k per head, contiguous
__device__ float g_ac[(size_t)BN_ALL*QL*QL];          // 512 MB: AC scores, then P in-place
__device__ float g_bd[(size_t)BN_ALL*QL*QL];          // 512 MB: BD_raw (unshifted)
__device__ float g_pv[(size_t)BN_ALL*QL*DH];          // attn_vec per (b,n)
__device__ float g_avr[(size_t)MR*DM];                // attn_vec repacked [row, n*64+d]
__device__ float g_attnout[(size_t)MR*DM];
__device__ float g_x[(size_t)MR*DM];
__device__ float g_h1[(size_t)MR*DI];
__device__ float g_core[(size_t)MR*DM];

// ---------------- generic tiled SGEMM: C = A(MxK) * B(KxN), row-major, batched -------
// BM=BN=64, BK=16, 256 threads, 4x4 per thread. Dims must be multiples of tiles (they are).
__global__ void __launch_bounds__(256) sgemm_nn(
    const float* __restrict__ A, const float* __restrict__ B, float* __restrict__ C,
    int M, int N, int K, size_t sA, size_t sB, size_t sC,
    const float* __restrict__ bias, int relu)
{
    A += (size_t)blockIdx.z * sA;
    B += (size_t)blockIdx.z * sB;
    C += (size_t)blockIdx.z * sC;
    __shared__ float As[16][64];
    __shared__ float Bs[16][64];
    const int tid = threadIdx.x;
    const int tx = tid & 15, ty = tid >> 4;
    const int m0 = blockIdx.y * 64, n0 = blockIdx.x * 64;
    const int ar = tid >> 2;        // 0..63
    const int ac4 = tid & 3;        // which float4 along k
    const int br = tid >> 4;        // 0..15
    const int bc4 = tid & 15;       // which float4 along n

    float acc[4][4];
    #pragma unroll
    for (int i = 0; i < 4; i++)
        #pragma unroll
        for (int j = 0; j < 4; j++) acc[i][j] = 0.f;

    for (int k0 = 0; k0 < K; k0 += 16) {
        float4 av = *(const float4*)&A[(size_t)(m0 + ar) * K + k0 + ac4 * 4];
        *(float4*)&Bs[br][bc4 * 4] = *(const float4*)&B[(size_t)(k0 + br) * N + n0 + bc4 * 4];
        As[ac4 * 4 + 0][ar] = av.x;
        As[ac4 * 4 + 1][ar] = av.y;
        As[ac4 * 4 + 2][ar] = av.z;
        As[ac4 * 4 + 3][ar] = av.w;
        __syncthreads();
        #pragma unroll
        for (int k = 0; k < 16; k++) {
            float a_[4], b_[4];
            *(float4*)a_ = *(const float4*)&As[k][ty * 4];
            *(float4*)b_ = *(const float4*)&Bs[k][tx * 4];
            #pragma unroll
            for (int i = 0; i < 4; i++)
                #pragma unroll
                for (int j = 0; j < 4; j++) acc[i][j] += a_[i] * b_[j];
        }
        __syncthreads();
    }

    #pragma unroll
    for (int i = 0; i < 4; i++) {
        const int m = m0 + ty * 4 + i;
        #pragma unroll
        for (int j = 0; j < 4; j++) {
            const int n = n0 + tx * 4 + j;
            float v = acc[i][j];
            if (bias) v += bias[n];
            if (relu) v = fmaxf(v, 0.f);
            C[(size_t)m * N + n] = v;
        }
    }
}

// C(MxN) = A(MxK) * B(NxK)^T, batched
__global__ void __launch_bounds__(256) sgemm_nt(
    const float* __restrict__ A, const float* __restrict__ B, float* __restrict__ C,
    int M, int N, int K, size_t sA, size_t sB, size_t sC)
{
    A += (size_t)blockIdx.z * sA;
    B += (size_t)blockIdx.z * sB;
    C += (size_t)blockIdx.z * sC;
    __shared__ float As[16][64];
    __shared__ float Bs[16][64];
    const int tid = threadIdx.x;
    const int tx = tid & 15, ty = tid >> 4;
    const int m0 = blockIdx.y * 64, n0 = blockIdx.x * 64;
    const int ar = tid >> 2;
    const int ac4 = tid & 3;

    float acc[4][4];
    #pragma unroll
    for (int i = 0; i < 4; i++)
        #pragma unroll
        for (int j = 0; j < 4; j++) acc[i][j] = 0.f;

    for (int k0 = 0; k0 < K; k0 += 16) {
        float4 av = *(const float4*)&A[(size_t)(m0 + ar) * K + k0 + ac4 * 4];
        float4 bv = *(const float4*)&B[(size_t)(n0 + ar) * K + k0 + ac4 * 4];
        As[ac4 * 4 + 0][ar] = av.x;
        As[ac4 * 4 + 1][ar] = av.y;
        As[ac4 * 4 + 2][ar] = av.z;
        As[ac4 * 4 + 3][ar] = av.w;
        Bs[ac4 * 4 + 0][ar] = bv.x;
        Bs[ac4 * 4 + 1][ar] = bv.y;
        Bs[ac4 * 4 + 2][ar] = bv.z;
        Bs[ac4 * 4 + 3][ar] = bv.w;
        __syncthreads();
        #pragma unroll
        for (int k = 0; k < 16; k++) {
            float a_[4], b_[4];
            *(float4*)a_ = *(const float4*)&As[k][ty * 4];
            *(float4*)b_ = *(const float4*)&Bs[k][tx * 4];
            #pragma unroll
            for (int i = 0; i < 4; i++)
                #pragma unroll
                for (int j = 0; j < 4; j++) acc[i][j] += a_[i] * b_[j];
        }
        __syncthreads();
    }

    #pragma unroll
    for (int i = 0; i < 4; i++) {
        const int m = m0 + ty * 4 + i;
        #pragma unroll
        for (int j = 0; j < 4; j++)
            C[(size_t)m * N + n0 + tx * 4 + j] = acc[i][j];
    }
}

// ---------------- repack q/k/v into contiguous per-(b,n) buffers ----------------
__global__ void repack_qkv(const float* __restrict__ rwb, const float* __restrict__ rrb)
{
    const int idx = blockIdx.x * blockDim.x + threadIdx.x;     // over 32*2048*64 = 2^22
    const int d = idx & 63;
    const int i = (idx >> 6) & (QL - 1);
    const int bn = idx >> 17;
    const int b = bn >> 4, n = bn & 15;
    const size_t src = (size_t)(i * BSZ + b) * (3 * DM) + n * DH + d;
    const float q = g_wheads[src];
    g_qw[idx] = q + rwb[n * DH + d];
    g_qr[idx] = q + rrb[n * DH + d];
    g_kc[idx] = g_wheads[src + DM];
    g_vc[idx] = g_wheads[src + 2 * DM];
}

__global__ void repack_rk(void)
{
    const int idx = blockIdx.x * blockDim.x + threadIdx.x;     // over 16*2048*64 = 2^21
    const int d = idx & 63;
    const int m = (idx >> 6) & (QL - 1);
    const int n = idx >> 17;
    g_rkc[idx] = g_rk[(size_t)m * DM + n * DH + d];
}

// ---------------- rel-shift + mask + softmax (in-place: writes P into g_ac) --------
// score[i,j] = scale*(AC[i,j] + BD_raw[i, j + (QL-1-i)]) for j<=i; softmax over j.
__global__ void softmax_shift(void)
{
    const int i = blockIdx.x;
    const int bn = blockIdx.y;
    float* ac = g_ac + (size_t)bn * QL * QL + (size_t)i * QL;
    const float* bd = g_bd + (size_t)bn * QL * QL + (size_t)i * QL;
    const int nvalid = i + 1;
    const int shift = QL - 1 - i;
    const float scale = 0.125f;
    __shared__ float red[256];
    const int tid = threadIdx.x;

    float lmax = -3.4e38f;
    for (int j = tid; j < nvalid; j += 256) {
        float s = (ac[j] + bd[j + shift]) * scale;
        lmax = fmaxf(lmax, s);
    }
    red[tid] = lmax; __syncthreads();
    for (int off = 128; off; off >>= 1) {
        if (tid < off) red[tid] = fmaxf(red[tid], red[tid + off]);
        __syncthreads();
    }
    const float rmax = red[0];
    __syncthreads();

    float lsum = 0.f;
    for (int j = tid; j < nvalid; j += 256) {
        float s = (ac[j] + bd[j + shift]) * scale;
        lsum += __expf(s - rmax);
    }
    red[tid] = lsum; __syncthreads();
    for (int off = 128; off; off >>= 1) {
        if (tid < off) red[tid] += red[tid + off];
        __syncthreads();
    }
    const float inv = 1.f / red[0];
    __syncthreads();

    for (int j = tid; j < QL; j += 256) {
        float p = 0.f;
        if (j < nvalid) {
            float s = (ac[j] + bd[j + shift]) * scale;
            p = __expf(s - rmax) * inv;
        }
        ac[j] = p;
    }
}

// ---------------- attn_vec repack: [b,n,i,d] -> [i*2+b, n*64+d] ----------------
__global__ void repack_av(void)
{
    const int idx = blockIdx.x * blockDim.x + threadIdx.x;     // over 4096*1024 = 2^22
    const int col = idx & 1023;
    const int n = col >> 6, d = col & 63;
    const int row = idx >> 10;
    const int i = row >> 1, b = row & 1;
    g_avr[idx] = g_pv[(size_t)((b << 4) | n) * QL * DH + (size_t)i * DH + d];
}

// ---------------- residual add + LayerNorm ----------------
__global__ void add_ln(const float* __restrict__ a, const float* __restrict__ bb,
                       const float* __restrict__ g, const float* __restrict__ beta,
                       float* __restrict__ out)
{
    const int row = blockIdx.x;
    const int tid = threadIdx.x;
    const float* pa = a + (size_t)row * DM;
    const float* pb = bb + (size_t)row * DM;
    __shared__ float red[256];
    float vals[4];
    float lsum = 0.f;
    #pragma unroll
    for (int t = 0; t < 4; t++) {
        const int c = tid + t * 256;
        float v = pa[c] + pb[c];
        vals[t] = v;
        lsum += v;
    }
    red[tid] = lsum; __syncthreads();
    for (int off = 128; off; off >>= 1) {
        if (tid < off) red[tid] += red[tid + off];
        __syncthreads();
    }
    const float mean = red[0] * (1.f / DM);
    __syncthreads();

    float lv = 0.f;
    #pragma unroll
    for (int t = 0; t < 4; t++) {
        float dlt = vals[t] - mean;
        lv += dlt * dlt;
    }
    red[tid] = lv; __syncthreads();
    for (int off = 128; off; off >>= 1) {
        if (tid < off) red[tid] += red[tid + off];
        __syncthreads();
    }
    const float rstd = rsqrtf(red[0] * (1.f / DM) + 1e-5f);
    __syncthreads();

    #pragma unroll
    for (int t = 0; t < 4; t++) {
        const int c = tid + t * 256;
        out[(size_t)row * DM + c] = (vals[t] - mean) * rstd * g[c] + beta[c];
    }
}

// ---------------- host launch ----------------
extern "C" void kernel_launch(void* const* d_in, const int* in_sizes, int n_in,
                              void* d_out, int out_size)
{
    (void)in_sizes; (void)n_in; (void)out_size;
    const float* w      = (const float*)d_in[0];
    const float* r      = (const float*)d_in[1];
    const float* rwb    = (const float*)d_in[2];
    const float* rrb    = (const float*)d_in[3];
    // d_in[4] = attn_mask (bool) — causal, reconstructed analytically
    const float* qkv_w  = (const float*)d_in[5];
    const float* rnet_w = (const float*)d_in[6];
    const float* o_w    = (const float*)d_in[7];
    const float* ln1g   = (const float*)d_in[8];
    const float* ln1b   = (const float*)d_in[9];
    const float* w1     = (const float*)d_in[10];
    const float* b1     = (const float*)d_in[11];
    const float* w2     = (const float*)d_in[12];
    const float* b2     = (const float*)d_in[13];
    const float* ln2g   = (const float*)d_in[14];
    const float* ln2b   = (const float*)d_in[15];
    float* out = (float*)d_out;

    float *wheads, *rk, *qw, *qr, *kc, *vc, *rkc, *acb, *bdb, *pv, *avr, *attnout, *x, *h1, *core;
    cudaGetSymbolAddress((void**)&wheads,  g_wheads);
    cudaGetSymbolAddress((void**)&rk,      g_rk);
    cudaGetSymbolAddress((void**)&qw,      g_qw);
    cudaGetSymbolAddress((void**)&qr,      g_qr);
    cudaGetSymbolAddress((void**)&kc,      g_kc);
    cudaGetSymbolAddress((void**)&vc,      g_vc);
    cudaGetSymbolAddress((void**)&rkc,     g_rkc);
    cudaGetSymbolAddress((void**)&acb,     g_ac);
    cudaGetSymbolAddress((void**)&bdb,     g_bd);
    cudaGetSymbolAddress((void**)&pv,      g_pv);
    cudaGetSymbolAddress((void**)&avr,     g_avr);
    cudaGetSymbolAddress((void**)&attnout, g_attnout);
    cudaGetSymbolAddress((void**)&x,       g_x);
    cudaGetSymbolAddress((void**)&h1,      g_h1);
    cudaGetSymbolAddress((void**)&core,    g_core);

    const size_t sQD = (size_t)QL * DH;     // 2048*64
    const size_t sQQ = (size_t)QL * QL;     // 2048*2048

    // 1. QKV projection: [4096,1024] @ [1024,3072]
    sgemm_nn<<<dim3(3072 / 64, 4096 / 64, 1), 256>>>(w, qkv_w, wheads, MR, 3 * DM, DM, 0, 0, 0, nullptr, 0);
    // 2. r projection: [2048,1024] @ [1024,1024]
    sgemm_nn<<<dim3(1024 / 64, 2048 / 64, 1), 256>>>(r, rnet_w, rk, QL, DM, DM, 0, 0, 0, nullptr, 0);
    // 3. repacks
    repack_qkv<<<(BN_ALL * QL * DH) / 256, 256>>>(rwb, rrb);
    repack_rk<<<(NH * QL * DH) / 256, 256>>>();
    // 4. AC = QW @ K^T, batched over 32 (b,n)
    sgemm_nt<<<dim3(32, 32, 32), 256>>>(qw, kc, acb, QL, QL, DH, sQD, sQD, sQQ);
    // 5. BD_raw = QR @ r_k^T — r_k batch is over n only, so two launches (b=0, b=1)
    sgemm_nt<<<dim3(32, 32, 16), 256>>>(qr, rkc, bdb, QL, QL, DH, sQD, sQD, sQQ);
    sgemm_nt<<<dim3(32, 32, 16), 256>>>(qr + (size_t)16 * sQD, rkc, bdb + (size_t)16 * sQQ,
                                        QL, QL, DH, sQD, sQD, sQQ);
    // 6. shift + mask + softmax (P written in-place into g_ac)
    softmax_shift<<<dim3(QL, BN_ALL), 256>>>();
    // 7. attn_vec = P @ V, batched
    sgemm_nn<<<dim3(1, 32, 32), 256>>>(acb, vc, pv, QL, DH, QL, sQQ, sQD, sQD, nullptr, 0);
    // 8. repack to [row, n*64+d], then output projection
    repack_av<<<(MR * DM) / 256, 256>>>();
    sgemm_nn<<<dim3(1024 / 64, 4096 / 64, 1), 256>>>(avr, o_w, attnout, MR, DM, DM, 0, 0, 0, nullptr, 0);
    // 9. x = LN(w + attn_out)
    add_ln<<<MR, 256>>>(w, attnout, ln1g, ln1b, x);
    // 10. FFN
    sgemm_nn<<<dim3(4096 / 64, 4096 / 64, 1), 256>>>(x, w1, h1, MR, DI, DM, 0, 0, 0, b1, 1);
    sgemm_nn<<<dim3(1024 / 64, 4096 / 64, 1), 256>>>(h1, w2, core, MR, DM, DI, 0, 0, 0, b2, 0);
    // 11. out = LN(x + core)
    add_ln<<<MR, 256>>>(x, core, ln2g, ln2b, out);
}

// round 2
// speedup vs baseline: 2.5127x; 2.5127x over previous
#include <cuda_runtime.h>
#include <cuda_bf16.h>
#include <math.h>
#include <stdint.h>

// Problem constants
#define QL 2048
#define BSZ 2
#define DM 1024
#define NH 16
#define DH 64
#define DI 4096
#define MR (QL*BSZ)      // 4096 rows of [row = i*2+b]
#define BN_ALL (BSZ*NH)  // 32 (b,n) pairs, bn = b*16+n

// ---------------- fp32 scratch ----------------
__device__ float g_wheads[(size_t)MR*3*DM];
__device__ float g_rk[(size_t)QL*DM];
__device__ float g_qw[(size_t)BN_ALL*QL*DH];
__device__ float g_qr[(size_t)BN_ALL*QL*DH];
__device__ float g_ac[(size_t)BN_ALL*QL*QL];          // AC scores, then P in-place
__device__ float g_bd[(size_t)BN_ALL*QL*QL];          // BD_raw (unshifted)
__device__ float g_pv[(size_t)BN_ALL*QL*DH];
__device__ float g_avr[(size_t)MR*DM];
__device__ float g_attnout[(size_t)MR*DM];
__device__ float g_x[(size_t)MR*DM];
__device__ float g_h1[(size_t)MR*DI];
__device__ float g_core[(size_t)MR*DM];

// ---------------- bf16 hi/lo split operand buffers (B side, [N][K] layouts) ---------
__device__ __nv_bfloat16 g_qkvwT_h[(size_t)3*DM*DM], g_qkvwT_l[(size_t)3*DM*DM];
__device__ __nv_bfloat16 g_rnetwT_h[(size_t)DM*DM],  g_rnetwT_l[(size_t)DM*DM];
__device__ __nv_bfloat16 g_owT_h[(size_t)DM*DM],     g_owT_l[(size_t)DM*DM];
__device__ __nv_bfloat16 g_w1T_h[(size_t)DI*DM],     g_w1T_l[(size_t)DI*DM];
__device__ __nv_bfloat16 g_w2T_h[(size_t)DM*DI],     g_w2T_l[(size_t)DM*DI];
__device__ __nv_bfloat16 g_kch[(size_t)BN_ALL*QL*DH], g_kcl[(size_t)BN_ALL*QL*DH];
__device__ __nv_bfloat16 g_rkch[(size_t)NH*QL*DH],    g_rkcl[(size_t)NH*QL*DH];
__device__ __nv_bfloat16 g_vth[(size_t)BN_ALL*DH*QL], g_vtl[(size_t)BN_ALL*DH*QL];

// ---------------- helpers ----------------
__device__ __forceinline__ unsigned smem_u32(const void* p) {
    return (unsigned)__cvta_generic_to_shared(p);
}
__device__ __forceinline__ void ldsm4(uint32_t& r0, uint32_t& r1, uint32_t& r2, uint32_t& r3, unsigned a) {
    asm volatile("ldmatrix.sync.aligned.m8n8.x4.shared.b16 {%0,%1,%2,%3}, [%4];"
                 : "=r"(r0), "=r"(r1), "=r"(r2), "=r"(r3) : "r"(a));
}
__device__ __forceinline__ void mma16816(float* c, const uint32_t* a, const uint32_t* b) {
    asm volatile("mma.sync.aligned.m16n8k16.row.col.f32.bf16.bf16.f32 "
                 "{%0,%1,%2,%3}, {%4,%5,%6,%7}, {%8,%9}, {%0,%1,%2,%3};"
                 : "+f"(c[0]), "+f"(c[1]), "+f"(c[2]), "+f"(c[3])
                 : "r"(a[0]), "r"(a[1]), "r"(a[2]), "r"(a[3]), "r"(b[0]), "r"(b[1]));
}
__device__ __forceinline__ void split1(float v, __nv_bfloat16& h, __nv_bfloat16& l) {
    h = __float2bfloat16(v);
    l = __float2bfloat16(v - __bfloat162float(h));
}

#define SKEW 24

// ======================================================================================
// C[M,N] = A[M,K](fp32,row) * Bt[N,K](bf16 hi/lo), fp32 out. Batched via blockIdx.z.
// BM=128 fixed, BN template (128 or 64). Warp tile 32x32. BK=16, double-buffered.
// tri: 0 none; 1 skip n0>=m0+BM (causal AC); 2 skip n0+BN+m0+BM<=QL (BD shifted);
//      3 causal K cap: kend=min(K, m0+BM)   (P@V)
// ======================================================================================
template<int BN>
__global__ void __launch_bounds__(BN*4, 1) gemm_bf16x3(
    const float* __restrict__ A, const __nv_bfloat16* __restrict__ Bh,
    const __nv_bfloat16* __restrict__ Bl, float* __restrict__ C,
    int M, int N, int K, size_t strA, size_t strB, size_t strC,
    const float* __restrict__ bias, int relu, int tri)
{
    constexpr int BM = 128;
    constexpr int NT = BN * 4;          // threads
    constexpr int NWN = BN / 32;        // warps along n
    constexpr int ACH = (BM * 4) / NT;  // A float4 chunks per thread (1 or 2)

    const int m0 = blockIdx.y * BM, n0 = blockIdx.x * BN;
    if (tri == 1 && n0 >= m0 + BM) return;
    if (tri == 2 && n0 + BN + m0 + BM <= QL) return;
    int kend = K;
    if (tri == 3) kend = min(K, m0 + BM);

    A  += (size_t)blockIdx.z * strA;
    Bh += (size_t)blockIdx.z * strB;
    Bl += (size_t)blockIdx.z * strB;
    C  += (size_t)blockIdx.z * strC;

    __shared__ __nv_bfloat16 sA[2][2][BM][SKEW];   // [stage][hi/lo][m][k]
    __shared__ __nv_bfloat16 sB[2][2][BN][SKEW];   // [stage][hi/lo][n][k]

    const int tid = threadIdx.x;
    const int lane = tid & 31, w = tid >> 5;
    const int wm = (w / NWN) * 32;
    const int wn = (w % NWN) * 32;

    float acc[2][4][4];
    #pragma unroll
    for (int mt = 0; mt < 2; mt++)
        #pragma unroll
        for (int nt = 0; nt < 4; nt++)
            #pragma unroll
            for (int e = 0; e < 4; e++) acc[mt][nt][e] = 0.f;

    // prefetch registers
    float4 pa[ACH];
    uint4 pb;

    // fetch indices (compile-time shapes)
    const int b_buf  = (tid >= BN * 2) ? 1 : 0;
    const int b_c    = tid - b_buf * BN * 2;
    const int b_row  = b_c >> 1;
    const int b_half = (b_c & 1) * 8;

    auto fetch = [&](int k0) {
        #pragma unroll
        for (int i = 0; i < ACH; i++) {
            const int idx = tid + i * NT;
            const int row = idx >> 2, c4 = (idx & 3) * 4;
            pa[i] = *(const float4*)(A + (size_t)(m0 + row) * K + k0 + c4);
        }
        const __nv_bfloat16* src = (b_buf ? Bl : Bh) + (size_t)(n0 + b_row) * K + k0 + b_half;
        pb = *(const uint4*)src;
    };
    auto commit = [&](int stg) {
        #pragma unroll
        for (int i = 0; i < ACH; i++) {
            const int idx = tid + i * NT;
            const int row = idx >> 2, c4 = (idx & 3) * 4;
            __nv_bfloat16 hx, lx, hy, ly, hz, lz, hw, lw;
            split1(pa[i].x, hx, lx); split1(pa[i].y, hy, ly);
            split1(pa[i].z, hz, lz); split1(pa[i].w, hw, lw);
            __nv_bfloat162* dh = (__nv_bfloat162*)&sA[stg][0][row][c4];
            __nv_bfloat162* dl = (__nv_bfloat162*)&sA[stg][1][row][c4];
            dh[0] = __nv_bfloat162(hx, hy); dh[1] = __nv_bfloat162(hz, hw);
            dl[0] = __nv_bfloat162(lx, ly); dl[1] = __nv_bfloat162(lz, lw);
        }
        *(uint4*)&sB[stg][b_buf][b_row][b_half] = pb;
    };

    fetch(0);
    commit(0);
    __syncthreads();

    const int nst = kend >> 4;
    for (int s = 0; s < nst; s++) {
        if (s + 1 < nst) fetch((s + 1) << 4);
        const int stg = s & 1;

        // load fragments
        uint32_t ah[2][4], al[2][4], bh[4][2], bl[4][2];
        #pragma unroll
        for (int mt = 0; mt < 2; mt++) {
            const int ar = wm + mt * 16 + (lane & 15);
            const int ac_ = (lane >> 4) * 8;
            ldsm4(ah[mt][0], ah[mt][1], ah[mt][2], ah[mt][3], smem_u32(&sA[stg][0][ar][ac_]));
            ldsm4(al[mt][0], al[mt][1], al[mt][2], al[mt][3], smem_u32(&sA[stg][1][ar][ac_]));
        }
        #pragma unroll
        for (int p = 0; p < 2; p++) {
            const int g = lane >> 3, l = lane & 7;
            const int br = wn + p * 16 + (g >> 1) * 8 + l;
            const int bc = (g & 1) * 8;
            uint32_t r0, r1, r2, r3;
            ldsm4(r0, r1, r2, r3, smem_u32(&sB[stg][0][br][bc]));
            bh[p * 2][0] = r0; bh[p * 2][1] = r1; bh[p * 2 + 1][0] = r2; bh[p * 2 + 1][1] = r3;
            ldsm4(r0, r1, r2, r3, smem_u32(&sB[stg][1][br][bc]));
            bl[p * 2][0] = r0; bl[p * 2][1] = r1; bl[p * 2 + 1][0] = r2; bl[p * 2 + 1][1] = r3;
        }

        #pragma unroll
        for (int mt = 0; mt < 2; mt++)
            #pragma unroll
            for (int nt = 0; nt < 4; nt++) {
                mma16816(acc[mt][nt], ah[mt], bh[nt]);
                mma16816(acc[mt][nt], ah[mt], bl[nt]);
                mma16816(acc[mt][nt], al[mt], bh[nt]);
            }

        if (s + 1 < nst) commit((s + 1) & 1);
        __syncthreads();
    }

    // epilogue
    #pragma unroll
    for (int mt = 0; mt < 2; mt++) {
        const int r0 = m0 + wm + mt * 16 + (lane >> 2);
        #pragma unroll
        for (int nt = 0; nt < 4; nt++) {
            const int c0 = n0 + wn + nt * 8 + (lane & 3) * 2;
            float v00 = acc[mt][nt][0], v01 = acc[mt][nt][1];
            float v10 = acc[mt][nt][2], v11 = acc[mt][nt][3];
            if (bias) {
                const float b0v = bias[c0], b1v = bias[c0 + 1];
                v00 += b0v; v01 += b1v; v10 += b0v; v11 += b1v;
            }
            if (relu) {
                v00 = fmaxf(v00, 0.f); v01 = fmaxf(v01, 0.f);
                v10 = fmaxf(v10, 0.f); v11 = fmaxf(v11, 0.f);
            }
            *(float2*)&C[(size_t)r0 * N + c0] = make_float2(v00, v01);
            *(float2*)&C[(size_t)(r0 + 8) * N + c0] = make_float2(v10, v11);
        }
    }
}

// ---------------- transpose + hi/lo split: in[R][C] fp32 -> hi/lo[C][R] bf16 --------
__global__ void splitT(const float* __restrict__ in, __nv_bfloat16* __restrict__ hi,
                       __nv_bfloat16* __restrict__ lo, int R, int C)
{
    __shared__ float t[32][33];
    const int bc = blockIdx.x * 32, br = blockIdx.y * 32;
    const int tx = threadIdx.x, ty = threadIdx.y;   // 32 x 8
    #pragma unroll
    for (int j = 0; j < 32; j += 8)
        t[ty + j][tx] = in[(size_t)(br + ty + j) * C + bc + tx];
    __syncthreads();
    #pragma unroll
    for (int j = 0; j < 32; j += 8) {
        const float v = t[tx][ty + j];
        __nv_bfloat16 h, l;
        split1(v, h, l);
        const size_t o = (size_t)(bc + ty + j) * R + br + tx;
        hi[o] = h; lo[o] = l;
    }
}

// ---------------- repack q/k/v ----------------
__global__ void repack_qkv(const float* __restrict__ rwb, const float* __restrict__ rrb)
{
    const int idx = blockIdx.x * blockDim.x + threadIdx.x;     // over 32*2048*64
    const int d = idx & 63;
    const int i = (idx >> 6) & (QL - 1);
    const int bn = idx >> 17;
    const int b = bn >> 4, n = bn & 15;
    const size_t src = (size_t)(i * BSZ + b) * (3 * DM) + n * DH + d;
    const float q = g_wheads[src];
    g_qw[idx] = q + rwb[n * DH + d];
    g_qr[idx] = q + rrb[n * DH + d];
    __nv_bfloat16 h, l;
    split1(g_wheads[src + DM], h, l);
    g_kch[idx] = h; g_kcl[idx] = l;
    split1(g_wheads[src + 2 * DM], h, l);
    const size_t vidx = (size_t)bn * DH * QL + (size_t)d * QL + i;   // [bn][d][i]
    g_vth[vidx] = h; g_vtl[vidx] = l;
}

__global__ void repack_rk(void)
{
    const int idx = blockIdx.x * blockDim.x + threadIdx.x;     // over 16*2048*64
    const int d = idx & 63;
    const int m = (idx >> 6) & (QL - 1);
    const int n = idx >> 17;
    __nv_bfloat16 h, l;
    split1(g_rk[(size_t)m * DM + n * DH + d], h, l);
    g_rkch[idx] = h; g_rkcl[idx] = l;
}

// ---------------- rel-shift + mask + softmax (in-place into g_ac) -------------------
__global__ void softmax_shift(void)
{
    const int i = blockIdx.x;
    const int bn = blockIdx.y;
    float* ac = g_ac + (size_t)bn * QL * QL + (size_t)i * QL;
    const float* bd = g_bd + (size_t)bn * QL * QL + (size_t)i * QL;
    const int nvalid = i + 1;
    const int shift = QL - 1 - i;
    const float scale = 0.125f;
    __shared__ float red[256];
    const int tid = threadIdx.x;

    float lmax = -3.4e38f;
    for (int j = tid; j < nvalid; j += 256) {
        float s = (ac[j] + bd[j + shift]) * scale;
        lmax = fmaxf(lmax, s);
    }
    red[tid] = lmax; __syncthreads();
    for (int off = 128; off; off >>= 1) {
        if (tid < off) red[tid] = fmaxf(red[tid], red[tid + off]);
        __syncthreads();
    }
    const float rmax = red[0];
    __syncthreads();

    float lsum = 0.f;
    for (int j = tid; j < nvalid; j += 256) {
        float s = (ac[j] + bd[j + shift]) * scale;
        lsum += __expf(s - rmax);
    }
    red[tid] = lsum; __syncthreads();
    for (int off = 128; off; off >>= 1) {
        if (tid < off) red[tid] += red[tid + off];
        __syncthreads();
    }
    const float inv = 1.f / red[0];
    __syncthreads();

    for (int j = tid; j < QL; j += 256) {
        float p = 0.f;
        if (j < nvalid) {
            float s = (ac[j] + bd[j + shift]) * scale;
            p = __expf(s - rmax) * inv;
        }
        ac[j] = p;
    }
}

// ---------------- attn_vec repack: [b,n,i,d] -> [i*2+b, n*64+d] ----------------
__global__ void repack_av(void)
{
    const int idx = blockIdx.x * blockDim.x + threadIdx.x;
    const int col = idx & 1023;
    const int n = col >> 6, d = col & 63;
    const int row = idx >> 10;
    const int i = row >> 1, b = row & 1;
    g_avr[idx] = g_pv[(size_t)((b << 4) | n) * QL * DH + (size_t)i * DH + d];
}

// ---------------- residual add + LayerNorm ----------------
__global__ void add_ln(const float* __restrict__ a, const float* __restrict__ bb,
                       const float* __restrict__ g, const float* __restrict__ beta,
                       float* __restrict__ out)
{
    const int row = blockIdx.x;
    const int tid = threadIdx.x;
    const float* pa = a + (size_t)row * DM;
    const float* pb = bb + (size_t)row * DM;
    __shared__ float red[256];
    float vals[4];
    float lsum = 0.f;
    #pragma unroll
    for (int t = 0; t < 4; t++) {
        const int c = tid + t * 256;
        float v = pa[c] + pb[c];
        vals[t] = v;
        lsum += v;
    }
    red[tid] = lsum; __syncthreads();
    for (int off = 128; off; off >>= 1) {
        if (tid < off) red[tid] += red[tid + off];
        __syncthreads();
    }
    const float mean = red[0] * (1.f / DM);
    __syncthreads();

    float lv = 0.f;
    #pragma unroll
    for (int t = 0; t < 4; t++) {
        float dlt = vals[t] - mean;
        lv += dlt * dlt;
    }
    red[tid] = lv; __syncthreads();
    for (int off = 128; off; off >>= 1) {
        if (tid < off) red[tid] += red[tid + off];
        __syncthreads();
    }
    const float rstd = rsqrtf(red[0] * (1.f / DM) + 1e-5f);
    __syncthreads();

    #pragma unroll
    for (int t = 0; t < 4; t++) {
        const int c = tid + t * 256;
        out[(size_t)row * DM + c] = (vals[t] - mean) * rstd * g[c] + beta[c];
    }
}

// ---------------- host launch ----------------
extern "C" void kernel_launch(void* const* d_in, const int* in_sizes, int n_in,
                              void* d_out, int out_size)
{
    (void)in_sizes; (void)n_in; (void)out_size;
    const float* w      = (const float*)d_in[0];
    const float* r      = (const float*)d_in[1];
    const float* rwb    = (const float*)d_in[2];
    const float* rrb    = (const float*)d_in[3];
    // d_in[4] = attn_mask (bool) — causal, handled analytically
    const float* qkv_w  = (const float*)d_in[5];
    const float* rnet_w = (const float*)d_in[6];
    const float* o_w    = (const float*)d_in[7];
    const float* ln1g   = (const float*)d_in[8];
    const float* ln1b   = (const float*)d_in[9];
    const float* w1     = (const float*)d_in[10];
    const float* b1     = (const float*)d_in[11];
    const float* w2     = (const float*)d_in[12];
    const float* b2     = (const float*)d_in[13];
    const float* ln2g   = (const float*)d_in[14];
    const float* ln2b   = (const float*)d_in[15];
    float* out = (float*)d_out;

    float *wheads, *rk, *qw, *qr, *acb, *bdb, *pv, *avr, *attnout, *x, *h1, *core;
    __nv_bfloat16 *qkvwTh, *qkvwTl, *rnetwTh, *rnetwTl, *owTh, *owTl;
    __nv_bfloat16 *w1Th, *w1Tl, *w2Th, *w2Tl;
    __nv_bfloat16 *kch, *kcl, *rkch, *rkcl, *vth, *vtl;
    cudaGetSymbolAddress((void**)&wheads,  g_wheads);
    cudaGetSymbolAddress((void**)&rk,      g_rk);
    cudaGetSymbolAddress((void**)&qw,      g_qw);
    cudaGetSymbolAddress((void**)&qr,      g_qr);
    cudaGetSymbolAddress((void**)&acb,     g_ac);
    cudaGetSymbolAddress((void**)&bdb,     g_bd);
    cudaGetSymbolAddress((void**)&pv,      g_pv);
    cudaGetSymbolAddress((void**)&avr,     g_avr);
    cudaGetSymbolAddress((void**)&attnout, g_attnout);
    cudaGetSymbolAddress((void**)&x,       g_x);
    cudaGetSymbolAddress((void**)&h1,      g_h1);
    cudaGetSymbolAddress((void**)&core,    g_core);
    cudaGetSymbolAddress((void**)&qkvwTh,  g_qkvwT_h);
    cudaGetSymbolAddress((void**)&qkvwTl,  g_qkvwT_l);
    cudaGetSymbolAddress((void**)&rnetwTh, g_rnetwT_h);
    cudaGetSymbolAddress((void**)&rnetwTl, g_rnetwT_l);
    cudaGetSymbolAddress((void**)&owTh,    g_owT_h);
    cudaGetSymbolAddress((void**)&owTl,    g_owT_l);
    cudaGetSymbolAddress((void**)&w1Th,    g_w1T_h);
    cudaGetSymbolAddress((void**)&w1Tl,    g_w1T_l);
    cudaGetSymbolAddress((void**)&w2Th,    g_w2T_h);
    cudaGetSymbolAddress((void**)&w2Tl,    g_w2T_l);
    cudaGetSymbolAddress((void**)&kch,     g_kch);
    cudaGetSymbolAddress((void**)&kcl,     g_kcl);
    cudaGetSymbolAddress((void**)&rkch,    g_rkch);
    cudaGetSymbolAddress((void**)&rkcl,    g_rkcl);
    cudaGetSymbolAddress((void**)&vth,     g_vth);
    cudaGetSymbolAddress((void**)&vtl,     g_vtl);

    const size_t sQD = (size_t)QL * DH;     // 2048*64
    const size_t sQQ = (size_t)QL * QL;     // 2048*2048
    const dim3 tb(32, 8);

    // 0. weight transpose + hi/lo split ([K][N] -> [N][K])
    splitT<<<dim3(3 * DM / 32, DM / 32), tb>>>(qkv_w,  qkvwTh,  qkvwTl,  DM, 3 * DM);
    splitT<<<dim3(DM / 32, DM / 32),     tb>>>(rnet_w, rnetwTh, rnetwTl, DM, DM);
    splitT<<<dim3(DM / 32, DM / 32),     tb>>>(o_w,    owTh,    owTl,    DM, DM);
    splitT<<<dim3(DI / 32, DM / 32),     tb>>>(w1,     w1Th,    w1Tl,    DM, DI);
    splitT<<<dim3(DM / 32, DI / 32),     tb>>>(w2,     w2Th,    w2Tl,    DI, DM);

    // 1. QKV projection: [4096,1024] x [1024,3072]
    gemm_bf16x3<128><<<dim3(3 * DM / 128, MR / 128, 1), 512>>>(
        w, qkvwTh, qkvwTl, wheads, MR, 3 * DM, DM, 0, 0, 0, nullptr, 0, 0);
    // 2. r projection: [2048,1024] x [1024,1024]
    gemm_bf16x3<128><<<dim3(DM / 128, QL / 128, 1), 512>>>(
        r, rnetwTh, rnetwTl, rk, QL, DM, DM, 0, 0, 0, nullptr, 0, 0);
    // 3. repacks (also produce bf16 hi/lo K and V^T, rk)
    repack_qkv<<<(BN_ALL * QL * DH) / 256, 256>>>(rwb, rrb);
    repack_rk<<<(NH * QL * DH) / 256, 256>>>();
    // 4. AC = QW @ K^T, batched over 32 (b,n), causal block skip
    gemm_bf16x3<128><<<dim3(QL / 128, QL / 128, BN_ALL), 512>>>(
        qw, kch, kcl, acb, QL, QL, DH, sQD, sQD, sQQ, nullptr, 0, 1);
    // 5. BD_raw = QR @ r_k^T, anti-diagonal block skip; two launches (b=0, b=1)
    gemm_bf16x3<128><<<dim3(QL / 128, QL / 128, NH), 512>>>(
        qr, rkch, rkcl, bdb, QL, QL, DH, sQD, sQD, sQQ, nullptr, 0, 2);
    gemm_bf16x3<128><<<dim3(QL / 128, QL / 128, NH), 512>>>(
        qr + (size_t)NH * sQD, rkch, rkcl, bdb + (size_t)NH * sQQ,
        QL, QL, DH, sQD, sQD, sQQ, nullptr, 0, 2);
    // 6. shift + mask + softmax (P in-place into g_ac)
    softmax_shift<<<dim3(QL, BN_ALL), 256>>>();
    // 7. attn_vec = P @ V (causal K cap), batched
    gemm_bf16x3<64><<<dim3(1, QL / 128, BN_ALL), 256>>>(
        acb, vth, vtl, pv, QL, DH, QL, sQQ, (size_t)DH * QL, sQD, nullptr, 0, 3);
    // 8. repack + output projection
    repack_av<<<(MR * DM) / 256, 256>>>();
    gemm_bf16x3<128><<<dim3(DM / 128, MR / 128, 1), 512>>>(
        avr, owTh, owTl, attnout, MR, DM, DM, 0, 0, 0, nullptr, 0, 0);
    // 9. x = LN(w + attn_out)
    add_ln<<<MR, 256>>>(w, attnout, ln1g, ln1b, x);
    // 10. FFN
    gemm_bf16x3<128><<<dim3(DI / 128, MR / 128, 1), 512>>>(
        x, w1Th, w1Tl, h1, MR, DI, DM, 0, 0, 0, b1, 1, 0);
    gemm_bf16x3<128><<<dim3(DM / 128, MR / 128, 1), 512>>>(
        h1, w2Th, w2Tl, core, MR, DM, DI, 0, 0, 0, b2, 0, 0);
    // 11. out = LN(x + core)
    add_ln<<<MR, 256>>>(x, core, ln2g, ln2b, out);
}